// round 14
// baseline (speedup 1.0000x reference)
#include <cuda_runtime.h>
#include <cuda_bf16.h>

#define IW 1280
#define IH 720
#define IB 32
#define WPC 8                    // warps per CTA
#define NCH 10                   // 128-px chunks per full row
#define HCH 5                    // chunks per half-row job
#define RING 512                 // floats per warp ring (4 chunk slots)

__global__ __launch_bounds__(WPC * 32) void warp_disp_ring2(
    const float* __restrict__ img,
    const float* __restrict__ disp,
    float* __restrict__ out)
{
    __shared__ float ring[WPC][RING];

    const int w    = threadIdx.x >> 5;
    const int lane = threadIdx.x & 31;
    const int l4   = lane * 4;
    const int j    = blockIdx.x * WPC + w;     // half-row job id
    const int rowi = j >> 1;                   // = b*IH + y
    const int half = j & 1;
    const int xb0  = half * (HCH * 128);       // 0 or 640
    const int y    = rowi % IH;
    const int b    = rowi / IH;
    float* rg = ring[w];

    // ---- vertical terms (uniform per warp): iy = y*H/(H-1) - 0.5 ----
    float iy  = fmaf((float)y, (float)IH / (float)(IH - 1), -0.5f);
    float y0f = floorf(iy);
    float wy1 = iy - y0f;
    float wy0 = 1.0f - wy1;
    int   y0  = (int)y0f;
    int   y1  = y0 + 1;
    bool  vy0 = (unsigned)y0 < (unsigned)IH;
    bool  vy1 = (unsigned)y1 < (unsigned)IH;

    const float* imgb = img + (size_t)b * (IH * IW);
    const float* r0p  = imgb + (vy0 ? y0 : 0) * IW;
    const float* r1p  = imgb + (vy1 ? y1 : 0) * IW;
    const float* dsp  = disp + (size_t)rowi * IW;
    float*       op   = out  + (size_t)rowi * IW;

    const float4 z4 = make_float4(0.f, 0.f, 0.f, 0.f);
    const float  Ax = (float)IW / (float)(IW - 1);

    // ---- prologue ----
    // chunk -1 (rel): zeros for half 0; last-68-float halo for half 1 (lanes >= 15)
    float4 hm = z4;
    if (half && lane >= 15) {
        int gx = xb0 - 128 + l4;               // 512+l4, in-bounds
        float4 a0 = vy0 ? *reinterpret_cast<const float4*>(r0p + gx) : z4;
        float4 a1 = vy1 ? *reinterpret_cast<const float4*>(r1p + gx) : z4;
        hm.x = fmaf(wy0, a0.x, wy1 * a1.x);
        hm.y = fmaf(wy0, a0.y, wy1 * a1.y);
        hm.z = fmaf(wy0, a0.z, wy1 * a1.z);
        hm.w = fmaf(wy0, a0.w, wy1 * a1.w);
    }
    *reinterpret_cast<float4*>(rg + l4) = hm;  // slot 0

    // chunk 0 (rel) loads -> store slot 1
    float4 a0 = vy0 ? *reinterpret_cast<const float4*>(r0p + xb0 + l4) : z4;
    float4 a1 = vy1 ? *reinterpret_cast<const float4*>(r1p + xb0 + l4) : z4;
    // chunk 1 (rel) loads (pipeline register B)
    float4 b0 = vy0 ? *reinterpret_cast<const float4*>(r0p + xb0 + 128 + l4) : z4;
    float4 b1 = vy1 ? *reinterpret_cast<const float4*>(r1p + xb0 + 128 + l4) : z4;
    {
        float4 h;
        h.x = fmaf(wy0, a0.x, wy1 * a1.x);
        h.y = fmaf(wy0, a0.y, wy1 * a1.y);
        h.z = fmaf(wy0, a0.z, wy1 * a1.z);
        h.w = fmaf(wy0, a0.w, wy1 * a1.w);
        *reinterpret_cast<float4*>(rg + 128 + l4) = h;
    }
    __syncwarp();

    // ---- main loop: iter s loads rel-chunk s+2, stores s+1, gathers s ----
#pragma unroll
    for (int s = 0; s < HCH; s++) {
        float4 A0 = z4, A1 = z4;
        if (s < HCH - 2) {                     // full load, always < NCH
            int gx = xb0 + (s + 2) * 128 + l4;
            if (vy0) A0 = *reinterpret_cast<const float4*>(r0p + gx);
            if (vy1) A1 = *reinterpret_cast<const float4*>(r1p + gx);
        } else if (s == HCH - 2) {             // rel-chunk 5: lane 0 only, half 0 only
            if (!half && lane == 0) {
                if (vy0) A0 = *reinterpret_cast<const float4*>(r0p + xb0 + 640);
                if (vy1) A1 = *reinterpret_cast<const float4*>(r1p + xb0 + 640);
            }
        }                                      // s == HCH-1: zeros (never consumed)
        float4 d4 = *reinterpret_cast<const float4*>(dsp + xb0 + s * 128 + l4);

        // store rel-chunk s+1 from B at slot ((s+2)&3)
        float4 h;
        h.x = fmaf(wy0, b0.x, wy1 * b1.x);
        h.y = fmaf(wy0, b0.y, wy1 * b1.y);
        h.z = fmaf(wy0, b0.z, wy1 * b1.z);
        h.w = fmaf(wy0, b0.w, wy1 * b1.w);
        *reinterpret_cast<float4*>(rg + ((s + 2) & 3) * 128 + l4) = h;
        __syncwarp();

        // gather rel-chunk s: taps span rel x in [s*128-65, s*128+128]
        const int xb = xb0 + s * 128 + l4;
        float dv[4] = {d4.x, d4.y, d4.z, d4.w};
        float res[4];
#pragma unroll
        for (int i = 0; i < 4; i++) {
            float u   = (float)(xb + i) - dv[i];
            float ix  = fmaf(u, Ax, -0.5f);
            float x0f = floorf(ix);
            float wx1 = ix - x0f;
            float wx0 = 1.0f - wx1;
            int   xr  = (int)x0f - xb0 + 128;  // in [63, 768]
            float v0 = rg[xr & (RING - 1)];
            float v1 = rg[(xr + 1) & (RING - 1)];
            res[i] = fmaf(v1, wx1, v0 * wx0);
        }
        *reinterpret_cast<float4*>(op + xb0 + s * 128 + l4) =
            make_float4(res[0], res[1], res[2], res[3]);
        __syncwarp();                          // protect slot (s-1)&3 from next store

        b0 = A0; b1 = A1;
    }
}

extern "C" void kernel_launch(void* const* d_in, const int* in_sizes, int n_in,
                              void* d_out, int out_size)
{
    const float* right_img = (const float*)d_in[0];
    const float* disp      = (const float*)d_in[1];
    float*       out       = (float*)d_out;

    const int jobs   = IB * IH * 2;            // 46080 half-row warp jobs
    const int blocks = jobs / WPC;             // 5760 CTAs
    warp_disp_ring2<<<blocks, WPC * 32>>>(right_img, disp, out);
}